// round 16
// baseline (speedup 1.0000x reference)
#include <cuda_runtime.h>
#include <math.h>
#include <stdint.h>

// ---------------- problem constants ----------------
#define B_    32
#define CIN   512
#define H_    38
#define W_    38
#define P_    1444          // 38*38
#define NO_   255
#define NPAD  256
#define STRIDE_F 16.0f

// ---------------- tiling ----------------
#define TM      128         // pixels per CTA
#define TN      128         // out-channels per CTA
#define KC      32          // k per chunk
#define NCHUNK  (CIN / KC)  // 16
#define STAGES  3

// A smem: V[k2(16)][m(128)] bf16x2, row stride 136 words (conflict-free frags)
#define A_LDW   136
#define A_BYTES (16 * A_LDW * 4)           // 8704
// B smem: pre-permuted fragment layout
#define B_BYTES (TN * KC * 2)              // 8192
#define STAGE_BYTES (A_BYTES + B_BYTES)    // 16896
#define SMEM_TOTAL  (STAGE_BYTES * STAGES) // 50688

__constant__ float c_aw[3] = {30.0f, 62.0f, 59.0f};
__constant__ float c_ah[3] = {61.0f, 45.0f, 119.0f};

// bf16 weights permuted into m16n8k16 B-fragment order:
// [n0Idx(2)][chunk(16)][wnIdx(2)][kst(2)][ntp(4)][lane(32)][v(4 uint32)]
__device__ uint32_t g_wperm[NPAD * CIN / 2];

static __device__ __forceinline__ uint32_t smem_u32(const void* p) {
    uint32_t a;
    asm("{ .reg .u64 t; cvta.to.shared.u64 t, %1; cvt.u32.u64 %0, t; }" : "=r"(a) : "l"(p));
    return a;
}
// pack {lo, hi} as bf16x2 (round-nearest)
static __device__ __forceinline__ uint32_t pack_bf16x2(float lo, float hi) {
    uint32_t r;
    asm("cvt.rn.bf16x2.f32 %0, %1, %2;" : "=r"(r) : "f"(hi), "f"(lo));
    return r;
}
static __device__ __forceinline__ void cp_async16(uint32_t dst, const void* src) {
    asm volatile("cp.async.cg.shared.global [%0], [%1], 16;" :: "r"(dst), "l"(src));
}
#define CP_COMMIT() asm volatile("cp.async.commit_group;" ::: "memory")
#define CP_WAIT1()  asm volatile("cp.async.wait_group 1;" ::: "memory")

static __device__ __forceinline__ void mma_bf16(float c[4], const uint32_t a[4],
                                                uint32_t b0, uint32_t b1) {
    asm volatile(
        "mma.sync.aligned.m16n8k16.row.col.f32.bf16.bf16.f32 "
        "{%0,%1,%2,%3}, {%4,%5,%6,%7}, {%8,%9}, {%0,%1,%2,%3};"
        : "+f"(c[0]), "+f"(c[1]), "+f"(c[2]), "+f"(c[3])
        : "r"(a[0]), "r"(a[1]), "r"(a[2]), "r"(a[3]), "r"(b0), "r"(b1));
}

// ---------------- pre-kernel: convert + permute weights to bf16 frags ----------------
__global__ void cvt_wgt_kernel(const float* __restrict__ wgt)
{
    int i = blockIdx.x * blockDim.x + threadIdx.x;   // 0 .. 65535 (uint32 slots)
    int v     = i & 3;
    int lane  = (i >> 2) & 31;
    int ntp   = (i >> 7) & 3;
    int kst   = (i >> 9) & 1;
    int wnIdx = (i >> 10) & 1;
    int chunk = (i >> 11) & 15;
    int n0Idx = i >> 15;
    int g  = lane >> 2;
    int t4 = lane & 3;
    int nt  = 2 * ntp + (v >> 1);
    int reg = v & 1;
    int n = n0Idx * 128 + wnIdx * 64 + nt * 8 + g;
    int k = chunk * 32 + kst * 16 + 2 * t4 + 8 * reg;
    float v0 = (n < NO_) ? wgt[n * CIN + k]     : 0.0f;
    float v1 = (n < NO_) ? wgt[n * CIN + k + 1] : 0.0f;
    g_wperm[i] = pack_bf16x2(v0, v1);
}

__global__ __launch_bounds__(256, 2)
void yolo_mma_bf16(const float* __restrict__ xin,
                   const float* __restrict__ bias, float* __restrict__ out)
{
    extern __shared__ char smem[];
    const uint32_t sbase = smem_u32(smem);
    const int tid  = threadIdx.x;
    const int wid  = tid >> 5;
    const int lane = tid & 31;
    const int g    = lane >> 2;
    const int t4   = lane & 3;
    const int p0   = blockIdx.x * TM;
    const int n0   = blockIdx.y * TN;
    const int b    = blockIdx.z;
    const float* xb = xin + (size_t)b * CIN * P_;

    const int wm    = (wid & 3) * 32;
    const int wnIdx = wid >> 2;

    float acc[2][8][4];
#pragma unroll
    for (int mt = 0; mt < 2; mt++)
#pragma unroll
        for (int nt = 0; nt < 8; nt++)
#pragma unroll
            for (int q = 0; q < 4; q++) acc[mt][nt][q] = 0.0f;

    // A loader: thread covers k-rows (r,r+1) and (r+16,r+17) at m-slot m4,
    // packing to bf16x2 immediately (8 regs per staged chunk).
    const int a_r  = 2 * (tid >> 5);    // 0..14 even
    const int a_m4 = tid & 31;
    const bool a_pred = (p0 + a_m4 * 4) < P_;

    auto ldgpackA = [&](int chunk, uint32_t w[8]) {
        const int k0 = chunk * KC;
        const float* s0 = xb + (size_t)(k0 + a_r) * P_ + p0 + a_m4 * 4;
        float4 v0, v1, v2, v3;
        if (a_pred) {
            v0 = *reinterpret_cast<const float4*>(s0);
            v1 = *reinterpret_cast<const float4*>(s0 + P_);
            v2 = *reinterpret_cast<const float4*>(s0 + (size_t)16 * P_);
            v3 = *reinterpret_cast<const float4*>(s0 + (size_t)17 * P_);
        } else {
            v0 = v1 = v2 = v3 = make_float4(0.f, 0.f, 0.f, 0.f);
        }
        w[0] = pack_bf16x2(v0.x, v1.x); w[1] = pack_bf16x2(v0.y, v1.y);
        w[2] = pack_bf16x2(v0.z, v1.z); w[3] = pack_bf16x2(v0.w, v1.w);
        w[4] = pack_bf16x2(v2.x, v3.x); w[5] = pack_bf16x2(v2.y, v3.y);
        w[6] = pack_bf16x2(v2.z, v3.z); w[7] = pack_bf16x2(v2.w, v3.w);
    };
    auto stsA = [&](int stage, const uint32_t w[8]) {
        const uint32_t base = sbase + stage * STAGE_BYTES;
        const int k2a = a_r >> 1;       // 0..7
        asm volatile("st.shared.v4.b32 [%0], {%1, %2, %3, %4};"
                     :: "r"(base + (uint32_t)(k2a * A_LDW + a_m4 * 4) * 4),
                        "r"(w[0]), "r"(w[1]), "r"(w[2]), "r"(w[3]) : "memory");
        asm volatile("st.shared.v4.b32 [%0], {%1, %2, %3, %4};"
                     :: "r"(base + (uint32_t)((k2a + 8) * A_LDW + a_m4 * 4) * 4),
                        "r"(w[4]), "r"(w[5]), "r"(w[6]), "r"(w[7]) : "memory");
    };
    const uint32_t* wsrc = g_wperm + (size_t)blockIdx.y * 32768;
    auto issueB = [&](int chunk, int stage) {
        const uint32_t bbase = sbase + stage * STAGE_BYTES + A_BYTES;
        const uint32_t* src = wsrc + (size_t)chunk * 2048;
#pragma unroll
        for (int j = 0; j < 2; j++) {
            int idx = tid + j * 256;
            cp_async16(bbase + (uint32_t)idx * 16, src + (size_t)idx * 4);
        }
    };

    // prologue: chunks 0,1 staged+stored; chunk 2 staged in regs; B 0,1 async
    uint32_t wbuf[2][8];
    ldgpackA(0, wbuf[0]); stsA(0, wbuf[0]);
    ldgpackA(1, wbuf[1]); stsA(1, wbuf[1]);
    ldgpackA(2, wbuf[0]);
    issueB(0, 0); CP_COMMIT();
    issueB(1, 1); CP_COMMIT();
    __syncthreads();

    for (int i = 0; i < NCHUNK; i++) {
        const int st = i % STAGES;
        CP_WAIT1();                   // B_i resident
        __syncthreads();              // stage (i+2)%3 free
        if (i + 2 < NCHUNK) {
            stsA((i + 2) % STAGES, wbuf[i & 1]);   // staged during iter i-1
            issueB(i + 2, (i + 2) % STAGES);
        }
        CP_COMMIT();
        if (i + 3 < NCHUNK) ldgpackA(i + 3, wbuf[(i + 1) & 1]);  // full-iter slack

        const uint32_t* V  = (const uint32_t*)(smem + (size_t)st * STAGE_BYTES);
        const uint4*    Bv = (const uint4*)(smem + (size_t)st * STAGE_BYTES + A_BYTES);

#pragma unroll
        for (int kst = 0; kst < 2; kst++) {
            const int kb2 = kst * 8;
            uint32_t af[2][4];
#pragma unroll
            for (int mt = 0; mt < 2; mt++) {
                const int mb = wm + mt * 16 + g;
                af[mt][0] = V[(kb2 + t4) * A_LDW + mb];
                af[mt][1] = V[(kb2 + t4) * A_LDW + mb + 8];
                af[mt][2] = V[(kb2 + t4 + 4) * A_LDW + mb];
                af[mt][3] = V[(kb2 + t4 + 4) * A_LDW + mb + 8];
            }
            const int bbase = (wnIdx * 2 + kst) * 128 + lane;
#pragma unroll
            for (int ntp = 0; ntp < 4; ntp++) {
                uint4 q = Bv[bbase + ntp * 32];
#pragma unroll
                for (int mt = 0; mt < 2; mt++) {
                    mma_bf16(acc[mt][ntp * 2 + 0], af[mt], q.x, q.y);
                    mma_bf16(acc[mt][ntp * 2 + 1], af[mt], q.z, q.w);
                }
            }
        }
    }

    // ---------------- fused YOLO decode epilogue ----------------
    const int wn = wnIdx * 64;
#pragma unroll
    for (int mt = 0; mt < 2; mt++) {
        const int r0 = wm + mt * 16 + g;
#pragma unroll
        for (int half = 0; half < 2; half++) {
            const int p = p0 + r0 + half * 8;
            if (p >= P_) continue;
            const float xo = (float)(p % W_);
            const float yo = (float)(p / W_);
            const size_t obase = ((size_t)b * P_ + p) * NO_;
#pragma unroll
            for (int nt = 0; nt < 8; nt++) {
#pragma unroll
                for (int q = 0; q < 2; q++) {
                    const int o = n0 + wn + nt * 8 + t4 * 2 + q;
                    if (o >= NO_) continue;
                    float v = acc[mt][nt][half * 2 + q] + __ldg(bias + o);
                    const int ai = (o >= 170) ? 2 : ((o >= 85) ? 1 : 0);
                    const int e = o - ai * 85;
                    float res;
                    if (e >= 4)      res = v;
                    else if (e == 0) res = (1.0f / (1.0f + __expf(-v)) + xo) * STRIDE_F;
                    else if (e == 1) res = (1.0f / (1.0f + __expf(-v)) + yo) * STRIDE_F;
                    else if (e == 2) res = __expf(v) * c_aw[ai];
                    else             res = __expf(v) * c_ah[ai];
                    out[obase + o] = res;
                }
            }
        }
    }
}

extern "C" void kernel_launch(void* const* d_in, const int* in_sizes, int n_in,
                              void* d_out, int out_size)
{
    const float* xin  = (const float*)d_in[0];
    const float* wgt  = (const float*)d_in[1];
    const float* bias = (const float*)d_in[2];
    float* out = (float*)d_out;

    cudaFuncSetAttribute(yolo_mma_bf16, cudaFuncAttributeMaxDynamicSharedMemorySize,
                         SMEM_TOTAL);

    cvt_wgt_kernel<<<(NPAD * CIN / 2) / 256, 256>>>(wgt);

    dim3 grid((P_ + TM - 1) / TM, 2, B_);   // 12 x 2 x 32 = 768 CTAs
    yolo_mma_bf16<<<grid, 256, SMEM_TOTAL>>>(xin, bias, out);
}